// round 11
// baseline (speedup 1.0000x reference)
#include <cuda_runtime.h>
#include <cuda_fp16.h>
#include <cstdint>

constexpr int Sc = 2048, Dc = 64;
constexpr int BM = 128, BN = 64, NT = 256;
constexpr int STR = 72;  // halves per smem row (144B: +16B skew -> conflict-free ldmatrix)

// smem layout (half offsets): Q hi/lo + double-buffered [Khi|Vhi] tiles
constexpr int QHI = 0, QLO = 9216;
constexpr int BUFH = 9216;            // halves per buffer: K 64*72 + V 64*72
constexpr int BUF0 = 18432;           // buffer b at BUF0 + b*BUFH; V at +4608 within
constexpr int SMEM_BYTES = (BUF0 + 2 * BUFH) * 2;  // 73728

#define DI __device__ __forceinline__

DI uint32_t h2u(__half2 h) { return *reinterpret_cast<uint32_t*>(&h); }

DI void mma16816(float* c, const uint32_t* a, const uint32_t* b) {
    asm volatile(
        "mma.sync.aligned.m16n8k16.row.col.f32.f16.f16.f32 "
        "{%0,%1,%2,%3}, {%4,%5,%6,%7}, {%8,%9}, {%0,%1,%2,%3};"
        : "+f"(c[0]), "+f"(c[1]), "+f"(c[2]), "+f"(c[3])
        : "r"(a[0]), "r"(a[1]), "r"(a[2]), "r"(a[3]), "r"(b[0]), "r"(b[1]));
}
DI void ldsm4(uint32_t* r, uint32_t a) {
    asm volatile("ldmatrix.sync.aligned.m8n8.x4.shared.b16 {%0,%1,%2,%3}, [%4];"
                 : "=r"(r[0]), "=r"(r[1]), "=r"(r[2]), "=r"(r[3]) : "r"(a));
}
DI void ldsm4t(uint32_t* r, uint32_t a) {
    asm volatile("ldmatrix.sync.aligned.m8n8.x4.trans.shared.b16 {%0,%1,%2,%3}, [%4];"
                 : "=r"(r[0]), "=r"(r[1]), "=r"(r[2]), "=r"(r[3]) : "r"(a));
}
DI float ex2(float x) { float y; asm("ex2.approx.ftz.f32 %0, %1;" : "=f"(y) : "f"(x)); return y; }

__global__ __launch_bounds__(NT, 2)
void fa_mma_kernel(const float* __restrict__ Q, const float* __restrict__ K,
                   const float* __restrict__ V, float* __restrict__ O) {
    extern __shared__ __half sm[];
    const int tid = threadIdx.x;
    const int lane = tid & 31, w = tid >> 5;
    const int r8 = lane & 7, g = lane >> 3;          // ldmatrix lane decomposition
    const int q4 = lane & 3, rr = lane >> 2;         // mma C-fragment decomposition
    const int head = blockIdx.y;
    const int m0 = (int)(gridDim.x - 1 - blockIdx.x) * BM;  // heavy tiles first
    const size_t hoff = (size_t)head * Sc * Dc;

    const uint32_t sb = (uint32_t)__cvta_generic_to_shared(sm);
    const uint32_t aq = sb + (uint32_t)(QHI + (16 * w + r8 + (g & 1) * 8) * STR + (g >> 1) * 8) * 2;
    // lane offsets relative to a buffer base (bytes)
    const uint32_t kb_rel = (uint32_t)((r8 + ((g >> 1) & 1) * 8) * STR + (g & 1) * 8) * 2;
    const uint32_t vb_rel = (uint32_t)(4608 + (r8 + (g & 1) * 8) * STR + (g >> 1) * 8) * 2;

    // ---- Q: load, scale, split hi/lo into smem (once) ----
    constexpr float SC = 0.125f * 1.4426950408889634f;  // 1/sqrt(64) * log2(e)
#pragma unroll
    for (int i = 0; i < 8; ++i) {
        int idx = tid + NT * i;                 // 0..2047
        int row = idx >> 4, dg = idx & 15;      // d = 4*dg
        float4 t = reinterpret_cast<const float4*>(Q + hoff + (size_t)(m0 + row) * Dc)[dg];
        t.x *= SC; t.y *= SC; t.z *= SC; t.w *= SC;
        __half2 h0 = __floats2half2_rn(t.x, t.y), h1 = __floats2half2_rn(t.z, t.w);
        __half2 l0 = __floats2half2_rn(t.x - __low2float(h0), t.y - __high2float(h0));
        __half2 l1 = __floats2half2_rn(t.z - __low2float(h1), t.w - __high2float(h1));
        __half2* ph = reinterpret_cast<__half2*>(sm + QHI + row * STR + 4 * dg);
        __half2* pl = reinterpret_cast<__half2*>(sm + QLO + row * STR + 4 * dg);
        ph[0] = h0; ph[1] = h1; pl[0] = l0; pl[1] = l1;
    }

    float oc[8][4];
#pragma unroll
    for (int j = 0; j < 8; ++j)
#pragma unroll
        for (int c = 0; c < 4; ++c) oc[j][c] = 0.0f;
    float lr0 = 0.0f, lr1 = 0.0f;   // per-thread partial row sums (quad-reduced at end)

    const int row0 = m0 + 16 * w + rr, row1 = row0 + 8;
    const int ntiles = m0 / BN + 2;

    // per-thread convert targets (same for every tile; buffer base varies)
    const int cv_key = tid >> 4, cv_dg = tid & 15;   // thread -> (key base, dim group)

    // ---- prologue: convert tile 0 into buffer 0 ----
#pragma unroll
    for (int i = 0; i < 4; ++i) {
        int key = cv_key + i * 16;
        float4 t = reinterpret_cast<const float4*>(K + hoff + (size_t)key * Dc)[cv_dg];
        float4 u = reinterpret_cast<const float4*>(V + hoff + (size_t)key * Dc)[cv_dg];
        __half2* ph = reinterpret_cast<__half2*>(sm + BUF0 + key * STR + 4 * cv_dg);
        ph[0] = __floats2half2_rn(t.x, t.y);
        ph[1] = __floats2half2_rn(t.z, t.w);
        __half2* qh = reinterpret_cast<__half2*>(sm + BUF0 + 4608 + key * STR + 4 * cv_dg);
        qh[0] = __floats2half2_rn(u.x, u.y);
        qh[1] = __floats2half2_rn(u.z, u.w);
    }
    __syncthreads();

    for (int jt = 0; jt < ntiles; ++jt) {
        const int j0 = jt * BN;
        const uint32_t bufb = sb + (uint32_t)(BUF0 + (jt & 1) * BUFH) * 2;
        const uint32_t kbase = bufb + kb_rel;
        const uint32_t vbase = bufb + vb_rel;

        // ---- S = (Qhi + Qlo) * Khi ----
        float sc[8][4];
#pragma unroll
        for (int j = 0; j < 8; ++j)
#pragma unroll
            for (int c = 0; c < 4; ++c) sc[j][c] = 0.0f;

#pragma unroll
        for (int t = 0; t < 4; ++t) {
            uint32_t ah[4], al[4];
            ldsm4(ah, aq + t * 32);
            ldsm4(al, aq + t * 32 + (QLO - QHI) * 2);
#pragma unroll
            for (int u = 0; u < 4; ++u) {
                uint32_t bh[4];
                ldsm4(bh, kbase + u * 2304 + t * 32);   // NON-trans: B[k][n] packed in k
                mma16816(sc[2 * u],     ah, bh);
                mma16816(sc[2 * u + 1], ah, bh + 2);
                mma16816(sc[2 * u],     al, bh);
                mma16816(sc[2 * u + 1], al, bh + 2);
            }
        }

        // ---- convert tile jt+1 into the other buffer (overlaps softmax/PV below) ----
        if (jt + 1 < ntiles) {
            const int nbase = j0 + BN;
            __half* dst = sm + BUF0 + ((jt + 1) & 1) * BUFH;
#pragma unroll
            for (int i = 0; i < 4; ++i) {
                int key = cv_key + i * 16;
                float4 t = reinterpret_cast<const float4*>(K + hoff + (size_t)(nbase + key) * Dc)[cv_dg];
                float4 u = reinterpret_cast<const float4*>(V + hoff + (size_t)(nbase + key) * Dc)[cv_dg];
                __half2* ph = reinterpret_cast<__half2*>(dst + key * STR + 4 * cv_dg);
                ph[0] = __floats2half2_rn(t.x, t.y);
                ph[1] = __floats2half2_rn(t.z, t.w);
                __half2* qh = reinterpret_cast<__half2*>(dst + 4608 + key * STR + 4 * cv_dg);
                qh[0] = __floats2half2_rn(u.x, u.y);
                qh[1] = __floats2half2_rn(u.z, u.w);
            }
        }

        // ---- softmax numerator: p = 2^s directly (scores bounded, fp32-safe) ----
        if (j0 + BN - 1 > m0) {  // diagonal tile: causal mask
            const int col0 = j0 + 2 * q4;
#pragma unroll
            for (int j = 0; j < 8; ++j) {
                int c0 = col0 + 8 * j;
                sc[j][0] = (c0     <= row0) ? sc[j][0] : -1e30f;
                sc[j][1] = (c0 + 1 <= row0) ? sc[j][1] : -1e30f;
                sc[j][2] = (c0     <= row1) ? sc[j][2] : -1e30f;
                sc[j][3] = (c0 + 1 <= row1) ? sc[j][3] : -1e30f;
            }
        }
#pragma unroll
        for (int j = 0; j < 8; ++j) {
            sc[j][0] = ex2(sc[j][0]); lr0 += sc[j][0];
            sc[j][1] = ex2(sc[j][1]); lr0 += sc[j][1];
            sc[j][2] = ex2(sc[j][2]); lr1 += sc[j][2];
            sc[j][3] = ex2(sc[j][3]); lr1 += sc[j][3];
        }

        // ---- O += (Phi + Plo) * Vhi ----
#pragma unroll
        for (int t = 0; t < 4; ++t) {
            uint32_t ph[4], pl[4];
            {
                __half2 h, l;
                h = __floats2half2_rn(sc[2 * t][0], sc[2 * t][1]);
                l = __floats2half2_rn(sc[2 * t][0] - __low2float(h), sc[2 * t][1] - __high2float(h));
                ph[0] = h2u(h); pl[0] = h2u(l);
                h = __floats2half2_rn(sc[2 * t][2], sc[2 * t][3]);
                l = __floats2half2_rn(sc[2 * t][2] - __low2float(h), sc[2 * t][3] - __high2float(h));
                ph[1] = h2u(h); pl[1] = h2u(l);
                h = __floats2half2_rn(sc[2 * t + 1][0], sc[2 * t + 1][1]);
                l = __floats2half2_rn(sc[2 * t + 1][0] - __low2float(h), sc[2 * t + 1][1] - __high2float(h));
                ph[2] = h2u(h); pl[2] = h2u(l);
                h = __floats2half2_rn(sc[2 * t + 1][2], sc[2 * t + 1][3]);
                l = __floats2half2_rn(sc[2 * t + 1][2] - __low2float(h), sc[2 * t + 1][3] - __high2float(h));
                ph[3] = h2u(h); pl[3] = h2u(l);
            }
#pragma unroll
            for (int j = 0; j < 8; j += 2) {
                uint32_t vh[4];
                ldsm4t(vh, vbase + t * 2304 + j * 16);  // trans: V rows (=k) -> B[k][n] packed in k
                mma16816(oc[j],     ph, vh);
                mma16816(oc[j + 1], ph, vh + 2);
                mma16816(oc[j],     pl, vh);
                mma16816(oc[j + 1], pl, vh + 2);
            }
        }

        __syncthreads();   // single barrier: publishes buf[(jt+1)&1], ends reads of buf[jt&1]
    }

    // ---- epilogue: quad-lane row-sum reduction, normalize, store ----
    lr0 += __shfl_xor_sync(0xffffffffu, lr0, 1);
    lr0 += __shfl_xor_sync(0xffffffffu, lr0, 2);
    lr1 += __shfl_xor_sync(0xffffffffu, lr1, 1);
    lr1 += __shfl_xor_sync(0xffffffffu, lr1, 2);
    const float i0 = 1.0f / lr0, i1 = 1.0f / lr1;
#pragma unroll
    for (int j = 0; j < 8; ++j) {
        int col = 8 * j + 2 * q4;
        reinterpret_cast<float2*>(O + hoff + (size_t)row0 * Dc + col)[0] =
            make_float2(oc[j][0] * i0, oc[j][1] * i0);
        reinterpret_cast<float2*>(O + hoff + (size_t)row1 * Dc + col)[0] =
            make_float2(oc[j][2] * i1, oc[j][3] * i1);
    }
}

extern "C" void kernel_launch(void* const* d_in, const int* in_sizes, int n_in,
                              void* d_out, int out_size) {
    const float* q = (const float*)d_in[0];
    const float* k = (const float*)d_in[1];
    const float* v = (const float*)d_in[2];
    float* o = (float*)d_out;

    cudaFuncSetAttribute(fa_mma_kernel, cudaFuncAttributeMaxDynamicSharedMemorySize, SMEM_BYTES);
    dim3 grid(Sc / BM, 2 * 12);
    fa_mma_kernel<<<grid, NT, SMEM_BYTES>>>(q, k, v, o);
}

// round 12
// speedup vs baseline: 1.7767x; 1.7767x over previous
#include <cuda_runtime.h>
#include <cuda_fp16.h>
#include <cstdint>

constexpr int Sc = 2048, Dc = 64;
constexpr int BM = 128, BN = 64, NT = 256;
constexpr int STR = 72;  // halves per smem row (144B: +16B skew -> conflict-free ldmatrix)

// smem layout (half offsets): Q hi/lo + double-buffered [Khi|Vhi] tiles
constexpr int QHI = 0, QLO = 9216;
constexpr int BUFH = 9216;            // halves per buffer: K 64*72 + V 64*72
constexpr int BUF0 = 18432;           // buffer b at BUF0 + b*BUFH; V at +4608 within
constexpr int SMEM_BYTES = (BUF0 + 2 * BUFH) * 2;  // 73728

#define DI __device__ __forceinline__

DI uint32_t h2u(__half2 h) { return *reinterpret_cast<uint32_t*>(&h); }

DI void mma16816(float* c, const uint32_t* a, const uint32_t* b) {
    asm volatile(
        "mma.sync.aligned.m16n8k16.row.col.f32.f16.f16.f32 "
        "{%0,%1,%2,%3}, {%4,%5,%6,%7}, {%8,%9}, {%0,%1,%2,%3};"
        : "+f"(c[0]), "+f"(c[1]), "+f"(c[2]), "+f"(c[3])
        : "r"(a[0]), "r"(a[1]), "r"(a[2]), "r"(a[3]), "r"(b[0]), "r"(b[1]));
}
DI void ldsm4(uint32_t* r, uint32_t a) {
    asm volatile("ldmatrix.sync.aligned.m8n8.x4.shared.b16 {%0,%1,%2,%3}, [%4];"
                 : "=r"(r[0]), "=r"(r[1]), "=r"(r[2]), "=r"(r[3]) : "r"(a));
}
DI void ldsm4t(uint32_t* r, uint32_t a) {
    asm volatile("ldmatrix.sync.aligned.m8n8.x4.trans.shared.b16 {%0,%1,%2,%3}, [%4];"
                 : "=r"(r[0]), "=r"(r[1]), "=r"(r[2]), "=r"(r[3]) : "r"(a));
}
DI float ex2(float x) { float y; asm("ex2.approx.ftz.f32 %0, %1;" : "=f"(y) : "f"(x)); return y; }

__global__ __launch_bounds__(NT, 2)
void fa_mma_kernel(const float* __restrict__ Q, const float* __restrict__ K,
                   const float* __restrict__ V, float* __restrict__ O) {
    extern __shared__ __half sm[];
    const int tid = threadIdx.x;
    const int lane = tid & 31, w = tid >> 5;
    const int r8 = lane & 7, g = lane >> 3;          // ldmatrix lane decomposition
    const int q4 = lane & 3, rr = lane >> 2;         // mma C-fragment decomposition
    const int head = blockIdx.y;
    const int m0 = (int)(gridDim.x - 1 - blockIdx.x) * BM;  // heavy tiles first
    const size_t hoff = (size_t)head * Sc * Dc;

    const uint32_t sb = (uint32_t)__cvta_generic_to_shared(sm);
    const uint32_t aq = sb + (uint32_t)(QHI + (16 * w + r8 + (g & 1) * 8) * STR + (g >> 1) * 8) * 2;
    // lane offsets relative to a buffer base (bytes)
    const uint32_t kb_rel = (uint32_t)((r8 + ((g >> 1) & 1) * 8) * STR + (g & 1) * 8) * 2;
    const uint32_t vb_rel = (uint32_t)(4608 + (r8 + (g & 1) * 8) * STR + (g >> 1) * 8) * 2;

    // ---- Q: load, scale, split hi/lo into smem (once) ----
    constexpr float SC = 0.125f * 1.4426950408889634f;  // 1/sqrt(64) * log2(e)
#pragma unroll
    for (int i = 0; i < 8; ++i) {
        int idx = tid + NT * i;                 // 0..2047
        int row = idx >> 4, dg = idx & 15;      // d = 4*dg
        float4 t = reinterpret_cast<const float4*>(Q + hoff + (size_t)(m0 + row) * Dc)[dg];
        t.x *= SC; t.y *= SC; t.z *= SC; t.w *= SC;
        __half2 h0 = __floats2half2_rn(t.x, t.y), h1 = __floats2half2_rn(t.z, t.w);
        __half2 l0 = __floats2half2_rn(t.x - __low2float(h0), t.y - __high2float(h0));
        __half2 l1 = __floats2half2_rn(t.z - __low2float(h1), t.w - __high2float(h1));
        __half2* ph = reinterpret_cast<__half2*>(sm + QHI + row * STR + 4 * dg);
        __half2* pl = reinterpret_cast<__half2*>(sm + QLO + row * STR + 4 * dg);
        ph[0] = h0; ph[1] = h1; pl[0] = l0; pl[1] = l1;
    }

    float oc[8][4];
#pragma unroll
    for (int j = 0; j < 8; ++j)
#pragma unroll
        for (int c = 0; c < 4; ++c) oc[j][c] = 0.0f;
    float mr0 = -1e30f, mr1 = -1e30f, lr0 = 0.0f, lr1 = 0.0f;

    const int row0 = m0 + 16 * w + rr, row1 = row0 + 8;
    const int ntiles = m0 / BN + 2;

    // per-thread convert targets (same for every tile; buffer base varies)
    const int cv_key = tid >> 4, cv_dg = tid & 15;   // thread -> (key base, dim group)

    // ---- prologue: convert tile 0 into buffer 0 ----
#pragma unroll
    for (int i = 0; i < 4; ++i) {
        int key = cv_key + i * 16;
        float4 t = reinterpret_cast<const float4*>(K + hoff + (size_t)key * Dc)[cv_dg];
        float4 u = reinterpret_cast<const float4*>(V + hoff + (size_t)key * Dc)[cv_dg];
        __half2* ph = reinterpret_cast<__half2*>(sm + BUF0 + key * STR + 4 * cv_dg);
        ph[0] = __floats2half2_rn(t.x, t.y);
        ph[1] = __floats2half2_rn(t.z, t.w);
        __half2* qh = reinterpret_cast<__half2*>(sm + BUF0 + 4608 + key * STR + 4 * cv_dg);
        qh[0] = __floats2half2_rn(u.x, u.y);
        qh[1] = __floats2half2_rn(u.z, u.w);
    }
    __syncthreads();

    for (int jt = 0; jt < ntiles; ++jt) {
        const int j0 = jt * BN;
        const uint32_t bufb = sb + (uint32_t)(BUF0 + (jt & 1) * BUFH) * 2;
        const uint32_t kbase = bufb + kb_rel;
        const uint32_t vbase = bufb + vb_rel;

        // ---- S = (Qhi + Qlo) * Khi ----
        float sc[8][4];
#pragma unroll
        for (int j = 0; j < 8; ++j)
#pragma unroll
            for (int c = 0; c < 4; ++c) sc[j][c] = 0.0f;

#pragma unroll
        for (int t = 0; t < 4; ++t) {
            uint32_t ah[4], al[4];
            ldsm4(ah, aq + t * 32);
            ldsm4(al, aq + t * 32 + (QLO - QHI) * 2);
#pragma unroll
            for (int u = 0; u < 4; ++u) {
                uint32_t bh[4];
                ldsm4(bh, kbase + u * 2304 + t * 32);   // NON-trans: B[k][n] packed in k
                mma16816(sc[2 * u],     ah, bh);
                mma16816(sc[2 * u + 1], ah, bh + 2);
                mma16816(sc[2 * u],     al, bh);
                mma16816(sc[2 * u + 1], al, bh + 2);
            }
        }

        // ---- convert tile jt+1 into the other buffer (overlaps softmax/PV below) ----
        if (jt + 1 < ntiles) {
            const int nbase = j0 + BN;
            __half* dst = sm + BUF0 + ((jt + 1) & 1) * BUFH;
#pragma unroll
            for (int i = 0; i < 4; ++i) {
                int key = cv_key + i * 16;
                float4 t = reinterpret_cast<const float4*>(K + hoff + (size_t)(nbase + key) * Dc)[cv_dg];
                float4 u = reinterpret_cast<const float4*>(V + hoff + (size_t)(nbase + key) * Dc)[cv_dg];
                __half2* ph = reinterpret_cast<__half2*>(dst + key * STR + 4 * cv_dg);
                ph[0] = __floats2half2_rn(t.x, t.y);
                ph[1] = __floats2half2_rn(t.z, t.w);
                __half2* qh = reinterpret_cast<__half2*>(dst + 4608 + key * STR + 4 * cv_dg);
                qh[0] = __floats2half2_rn(u.x, u.y);
                qh[1] = __floats2half2_rn(u.z, u.w);
            }
        }

        // ---- online softmax (rows row0, row1; cols spread over quad lanes) ----
        if (j0 + BN - 1 > m0) {  // diagonal tile: causal mask
            const int col0 = j0 + 2 * q4;
#pragma unroll
            for (int j = 0; j < 8; ++j) {
                int c0 = col0 + 8 * j;
                sc[j][0] = (c0     <= row0) ? sc[j][0] : -1e30f;
                sc[j][1] = (c0 + 1 <= row0) ? sc[j][1] : -1e30f;
                sc[j][2] = (c0     <= row1) ? sc[j][2] : -1e30f;
                sc[j][3] = (c0 + 1 <= row1) ? sc[j][3] : -1e30f;
            }
        }
        float mx0 = -1e30f, mx1 = -1e30f;
#pragma unroll
        for (int j = 0; j < 8; ++j) {
            mx0 = fmaxf(mx0, fmaxf(sc[j][0], sc[j][1]));
            mx1 = fmaxf(mx1, fmaxf(sc[j][2], sc[j][3]));
        }
        mx0 = fmaxf(mx0, __shfl_xor_sync(0xffffffffu, mx0, 1));
        mx0 = fmaxf(mx0, __shfl_xor_sync(0xffffffffu, mx0, 2));
        mx1 = fmaxf(mx1, __shfl_xor_sync(0xffffffffu, mx1, 1));
        mx1 = fmaxf(mx1, __shfl_xor_sync(0xffffffffu, mx1, 2));
        const float mn0 = fmaxf(mr0, mx0), mn1 = fmaxf(mr1, mx1);
        const float al0 = ex2(mr0 - mn0), al1 = ex2(mr1 - mn1);
        mr0 = mn0; mr1 = mn1;

        float s0 = 0.0f, s1 = 0.0f;
#pragma unroll
        for (int j = 0; j < 8; ++j) {
            sc[j][0] = ex2(sc[j][0] - mn0); s0 += sc[j][0];
            sc[j][1] = ex2(sc[j][1] - mn0); s0 += sc[j][1];
            sc[j][2] = ex2(sc[j][2] - mn1); s1 += sc[j][2];
            sc[j][3] = ex2(sc[j][3] - mn1); s1 += sc[j][3];
        }
        s0 += __shfl_xor_sync(0xffffffffu, s0, 1);
        s0 += __shfl_xor_sync(0xffffffffu, s0, 2);
        s1 += __shfl_xor_sync(0xffffffffu, s1, 1);
        s1 += __shfl_xor_sync(0xffffffffu, s1, 2);
        lr0 = lr0 * al0 + s0;
        lr1 = lr1 * al1 + s1;

        // rescale O accumulators
#pragma unroll
        for (int j = 0; j < 8; ++j) {
            oc[j][0] *= al0; oc[j][1] *= al0;
            oc[j][2] *= al1; oc[j][3] *= al1;
        }

        // ---- O += Phi * Vhi (P in [0,1]; fp16 quantization ~2^-11 rel, within budget) ----
#pragma unroll
        for (int t = 0; t < 4; ++t) {
            uint32_t ph[4];
            ph[0] = h2u(__floats2half2_rn(sc[2 * t][0],     sc[2 * t][1]));
            ph[1] = h2u(__floats2half2_rn(sc[2 * t][2],     sc[2 * t][3]));
            ph[2] = h2u(__floats2half2_rn(sc[2 * t + 1][0], sc[2 * t + 1][1]));
            ph[3] = h2u(__floats2half2_rn(sc[2 * t + 1][2], sc[2 * t + 1][3]));
#pragma unroll
            for (int j = 0; j < 8; j += 2) {
                uint32_t vh[4];
                ldsm4t(vh, vbase + t * 2304 + j * 16);  // trans: V rows (=k) -> B[k][n] packed in k
                mma16816(oc[j],     ph, vh);
                mma16816(oc[j + 1], ph, vh + 2);
            }
        }

        __syncthreads();   // single barrier: publishes buf[(jt+1)&1], ends reads of buf[jt&1]
    }

    // ---- epilogue ----
    const float i0 = 1.0f / lr0, i1 = 1.0f / lr1;
#pragma unroll
    for (int j = 0; j < 8; ++j) {
        int col = 8 * j + 2 * q4;
        reinterpret_cast<float2*>(O + hoff + (size_t)row0 * Dc + col)[0] =
            make_float2(oc[j][0] * i0, oc[j][1] * i0);
        reinterpret_cast<float2*>(O + hoff + (size_t)row1 * Dc + col)[0] =
            make_float2(oc[j][2] * i1, oc[j][3] * i1);
    }
}

extern "C" void kernel_launch(void* const* d_in, const int* in_sizes, int n_in,
                              void* d_out, int out_size) {
    const float* q = (const float*)d_in[0];
    const float* k = (const float*)d_in[1];
    const float* v = (const float*)d_in[2];
    float* o = (float*)d_out;

    cudaFuncSetAttribute(fa_mma_kernel, cudaFuncAttributeMaxDynamicSharedMemorySize, SMEM_BYTES);
    dim3 grid(Sc / BM, 2 * 12);
    fa_mma_kernel<<<grid, NT, SMEM_BYTES>>>(q, k, v, o);
}

// round 14
// speedup vs baseline: 1.8625x; 1.0483x over previous
#include <cuda_runtime.h>
#include <cuda_fp16.h>
#include <cstdint>

constexpr int Sc = 2048, Dc = 64;
constexpr int BM = 128, BN = 64, NT = 256;
constexpr int STR = 72;  // halves per smem row (144B: +16B skew -> conflict-free ldmatrix)

// smem layout (half offsets): Q hi/lo + double-buffered [Khi|Vhi] tiles
constexpr int QHI = 0, QLO = 9216;
constexpr int BUFH = 9216;            // halves per buffer: K 64*72 + V 64*72
constexpr int BUF0 = 18432;           // buffer b at BUF0 + b*BUFH; V at +4608 within
constexpr int SMEM_BYTES = (BUF0 + 2 * BUFH) * 2;  // 73728

#define DI __device__ __forceinline__

DI uint32_t h2u(__half2 h) { return *reinterpret_cast<uint32_t*>(&h); }

DI void mma16816(float* c, const uint32_t* a, const uint32_t* b) {
    asm volatile(
        "mma.sync.aligned.m16n8k16.row.col.f32.f16.f16.f32 "
        "{%0,%1,%2,%3}, {%4,%5,%6,%7}, {%8,%9}, {%0,%1,%2,%3};"
        : "+f"(c[0]), "+f"(c[1]), "+f"(c[2]), "+f"(c[3])
        : "r"(a[0]), "r"(a[1]), "r"(a[2]), "r"(a[3]), "r"(b[0]), "r"(b[1]));
}
DI void ldsm4(uint32_t* r, uint32_t a) {
    asm volatile("ldmatrix.sync.aligned.m8n8.x4.shared.b16 {%0,%1,%2,%3}, [%4];"
                 : "=r"(r[0]), "=r"(r[1]), "=r"(r[2]), "=r"(r[3]) : "r"(a));
}
DI void ldsm4t(uint32_t* r, uint32_t a) {
    asm volatile("ldmatrix.sync.aligned.m8n8.x4.trans.shared.b16 {%0,%1,%2,%3}, [%4];"
                 : "=r"(r[0]), "=r"(r[1]), "=r"(r[2]), "=r"(r[3]) : "r"(a));
}
DI float ex2(float x) { float y; asm("ex2.approx.ftz.f32 %0, %1;" : "=f"(y) : "f"(x)); return y; }

__global__ __launch_bounds__(NT, 2)
void fa_mma_kernel(const float* __restrict__ Q, const float* __restrict__ K,
                   const float* __restrict__ V, float* __restrict__ O) {
    extern __shared__ __half sm[];
    const int tid = threadIdx.x;
    const int lane = tid & 31, w = tid >> 5;
    const int r8 = lane & 7, g = lane >> 3;          // ldmatrix lane decomposition
    const int q4 = lane & 3, rr = lane >> 2;         // mma C-fragment decomposition
    const int head = blockIdx.y;
    const int m0 = (int)(gridDim.x - 1 - blockIdx.x) * BM;  // heavy tiles first
    const size_t hoff = (size_t)head * Sc * Dc;

    const uint32_t sb = (uint32_t)__cvta_generic_to_shared(sm);
    const uint32_t aq = sb + (uint32_t)(QHI + (16 * w + r8 + (g & 1) * 8) * STR + (g >> 1) * 8) * 2;
    // lane offsets relative to a buffer base (bytes)
    const uint32_t kb_rel = (uint32_t)((r8 + ((g >> 1) & 1) * 8) * STR + (g & 1) * 8) * 2;
    const uint32_t vb_rel = (uint32_t)(4608 + (r8 + (g & 1) * 8) * STR + (g >> 1) * 8) * 2;

    // ---- Q: load, scale, split hi/lo into smem (once) ----
    constexpr float SC = 0.125f * 1.4426950408889634f;  // 1/sqrt(64) * log2(e)
#pragma unroll
    for (int i = 0; i < 8; ++i) {
        int idx = tid + NT * i;                 // 0..2047
        int row = idx >> 4, dg = idx & 15;      // d = 4*dg
        float4 t = reinterpret_cast<const float4*>(Q + hoff + (size_t)(m0 + row) * Dc)[dg];
        t.x *= SC; t.y *= SC; t.z *= SC; t.w *= SC;
        __half2 h0 = __floats2half2_rn(t.x, t.y), h1 = __floats2half2_rn(t.z, t.w);
        __half2 l0 = __floats2half2_rn(t.x - __low2float(h0), t.y - __high2float(h0));
        __half2 l1 = __floats2half2_rn(t.z - __low2float(h1), t.w - __high2float(h1));
        __half2* ph = reinterpret_cast<__half2*>(sm + QHI + row * STR + 4 * dg);
        __half2* pl = reinterpret_cast<__half2*>(sm + QLO + row * STR + 4 * dg);
        ph[0] = h0; ph[1] = h1; pl[0] = l0; pl[1] = l1;
    }

    float oc[8][4];
#pragma unroll
    for (int j = 0; j < 8; ++j)
#pragma unroll
        for (int c = 0; c < 4; ++c) oc[j][c] = 0.0f;
    float mr0 = -1e30f, mr1 = -1e30f;
    float lr0 = 0.0f, lr1 = 0.0f;   // thread-local quad-partials; reduced once in epilogue

    const int row0 = m0 + 16 * w + rr, row1 = row0 + 8;
    const int ntiles = m0 / BN + 2;

    // per-thread convert targets (same for every tile; buffer base varies)
    const int cv_key = tid >> 4, cv_dg = tid & 15;   // thread -> (key base, dim group)

    // ---- prologue: convert tile 0 into buffer 0 ----
#pragma unroll
    for (int i = 0; i < 4; ++i) {
        int key = cv_key + i * 16;
        float4 t = reinterpret_cast<const float4*>(K + hoff + (size_t)key * Dc)[cv_dg];
        float4 u = reinterpret_cast<const float4*>(V + hoff + (size_t)key * Dc)[cv_dg];
        __half2* ph = reinterpret_cast<__half2*>(sm + BUF0 + key * STR + 4 * cv_dg);
        ph[0] = __floats2half2_rn(t.x, t.y);
        ph[1] = __floats2half2_rn(t.z, t.w);
        __half2* qh = reinterpret_cast<__half2*>(sm + BUF0 + 4608 + key * STR + 4 * cv_dg);
        qh[0] = __floats2half2_rn(u.x, u.y);
        qh[1] = __floats2half2_rn(u.z, u.w);
    }
    __syncthreads();

    for (int jt = 0; jt < ntiles; ++jt) {
        const int j0 = jt * BN;
        const uint32_t bufb = sb + (uint32_t)(BUF0 + (jt & 1) * BUFH) * 2;
        const uint32_t kbase = bufb + kb_rel;
        const uint32_t vbase = bufb + vb_rel;

        // ---- S = (Qhi + Qlo) * Khi ----
        float sc[8][4];
#pragma unroll
        for (int j = 0; j < 8; ++j)
#pragma unroll
            for (int c = 0; c < 4; ++c) sc[j][c] = 0.0f;

#pragma unroll
        for (int t = 0; t < 4; ++t) {
            uint32_t ah[4], al[4];
            ldsm4(ah, aq + t * 32);
            ldsm4(al, aq + t * 32 + (QLO - QHI) * 2);
#pragma unroll
            for (int u = 0; u < 4; ++u) {
                uint32_t bh[4];
                ldsm4(bh, kbase + u * 2304 + t * 32);   // NON-trans: B[k][n] packed in k
                mma16816(sc[2 * u],     ah, bh);
                mma16816(sc[2 * u + 1], ah, bh + 2);
                mma16816(sc[2 * u],     al, bh);
                mma16816(sc[2 * u + 1], al, bh + 2);
            }
        }

        // ---- convert tile jt+1 into the other buffer (overlaps softmax/PV below) ----
        if (jt + 1 < ntiles) {
            const int nbase = j0 + BN;
            __half* dst = sm + BUF0 + ((jt + 1) & 1) * BUFH;
#pragma unroll
            for (int i = 0; i < 4; ++i) {
                int key = cv_key + i * 16;
                float4 t = reinterpret_cast<const float4*>(K + hoff + (size_t)(nbase + key) * Dc)[cv_dg];
                float4 u = reinterpret_cast<const float4*>(V + hoff + (size_t)(nbase + key) * Dc)[cv_dg];
                __half2* ph = reinterpret_cast<__half2*>(dst + key * STR + 4 * cv_dg);
                ph[0] = __floats2half2_rn(t.x, t.y);
                ph[1] = __floats2half2_rn(t.z, t.w);
                __half2* qh = reinterpret_cast<__half2*>(dst + 4608 + key * STR + 4 * cv_dg);
                qh[0] = __floats2half2_rn(u.x, u.y);
                qh[1] = __floats2half2_rn(u.z, u.w);
            }
        }

        // ---- mask (diagonal tiles) + row max + quad max-reduce + rescale ----
        if (j0 + BN - 1 > m0) {
            const int col0 = j0 + 2 * q4;
#pragma unroll
            for (int j = 0; j < 8; ++j) {
                int c0 = col0 + 8 * j;
                sc[j][0] = (c0     <= row0) ? sc[j][0] : -1e30f;
                sc[j][1] = (c0 + 1 <= row0) ? sc[j][1] : -1e30f;
                sc[j][2] = (c0     <= row1) ? sc[j][2] : -1e30f;
                sc[j][3] = (c0 + 1 <= row1) ? sc[j][3] : -1e30f;
            }
        }
        float mx0 = -1e30f, mx1 = -1e30f;
#pragma unroll
        for (int j = 0; j < 8; ++j) {
            mx0 = fmaxf(mx0, fmaxf(sc[j][0], sc[j][1]));
            mx1 = fmaxf(mx1, fmaxf(sc[j][2], sc[j][3]));
        }
        mx0 = fmaxf(mx0, __shfl_xor_sync(0xffffffffu, mx0, 1));
        mx0 = fmaxf(mx0, __shfl_xor_sync(0xffffffffu, mx0, 2));
        mx1 = fmaxf(mx1, __shfl_xor_sync(0xffffffffu, mx1, 1));
        mx1 = fmaxf(mx1, __shfl_xor_sync(0xffffffffu, mx1, 2));
        const float mn0 = fmaxf(mr0, mx0), mn1 = fmaxf(mr1, mx1);
        const float al0 = ex2(mr0 - mn0), al1 = ex2(mr1 - mn1);
        mr0 = mn0; mr1 = mn1;

#pragma unroll
        for (int j = 0; j < 8; ++j) {
            oc[j][0] *= al0; oc[j][1] *= al0;
            oc[j][2] *= al1; oc[j][3] *= al1;
        }
        float s0 = 0.0f, s1 = 0.0f;

        // ---- fused softmax + PV per 16-key chunk: ex2 -> pack -> mma ----
#pragma unroll
        for (int t = 0; t < 4; ++t) {
            float p00 = ex2(sc[2 * t][0]     - mn0), p01 = ex2(sc[2 * t][1]     - mn0);
            float p02 = ex2(sc[2 * t][2]     - mn1), p03 = ex2(sc[2 * t][3]     - mn1);
            float p10 = ex2(sc[2 * t + 1][0] - mn0), p11 = ex2(sc[2 * t + 1][1] - mn0);
            float p12 = ex2(sc[2 * t + 1][2] - mn1), p13 = ex2(sc[2 * t + 1][3] - mn1);
            s0 += p00 + p01 + p10 + p11;
            s1 += p02 + p03 + p12 + p13;

            uint32_t ph[4];
            ph[0] = h2u(__floats2half2_rn(p00, p01));
            ph[1] = h2u(__floats2half2_rn(p02, p03));
            ph[2] = h2u(__floats2half2_rn(p10, p11));
            ph[3] = h2u(__floats2half2_rn(p12, p13));
#pragma unroll
            for (int j = 0; j < 8; j += 2) {
                uint32_t vh[4];
                ldsm4t(vh, vbase + t * 2304 + j * 16);  // trans: V rows (=k) -> B[k][n] packed in k
                mma16816(oc[j],     ph, vh);
                mma16816(oc[j + 1], ph, vh + 2);
            }
        }

        // thread-local l update (alpha is quad-uniform; reduce once at the end)
        lr0 = lr0 * al0 + s0;
        lr1 = lr1 * al1 + s1;

        __syncthreads();   // single barrier: publishes buf[(jt+1)&1], ends reads of buf[jt&1]
    }

    // ---- epilogue: quad-lane l reduction, normalize, store ----
    lr0 += __shfl_xor_sync(0xffffffffu, lr0, 1);
    lr0 += __shfl_xor_sync(0xffffffffu, lr0, 2);
    lr1 += __shfl_xor_sync(0xffffffffu, lr1, 1);
    lr1 += __shfl_xor_sync(0xffffffffu, lr1, 2);
    const float i0 = 1.0f / lr0, i1 = 1.0f / lr1;
#pragma unroll
    for (int j = 0; j < 8; ++j) {
        int col = 8 * j + 2 * q4;
        reinterpret_cast<float2*>(O + hoff + (size_t)row0 * Dc + col)[0] =
            make_float2(oc[j][0] * i0, oc[j][1] * i0);
        reinterpret_cast<float2*>(O + hoff + (size_t)row1 * Dc + col)[0] =
            make_float2(oc[j][2] * i1, oc[j][3] * i1);
    }
}

extern "C" void kernel_launch(void* const* d_in, const int* in_sizes, int n_in,
                              void* d_out, int out_size) {
    const float* q = (const float*)d_in[0];
    const float* k = (const float*)d_in[1];
    const float* v = (const float*)d_in[2];
    float* o = (float*)d_out;

    cudaFuncSetAttribute(fa_mma_kernel, cudaFuncAttributeMaxDynamicSharedMemorySize, SMEM_BYTES);
    dim3 grid(Sc / BM, 2 * 12);
    fa_mma_kernel<<<grid, NT, SMEM_BYTES>>>(q, k, v, o);
}

// round 15
// speedup vs baseline: 2.1940x; 1.1779x over previous
#include <cuda_runtime.h>
#include <cuda_fp16.h>
#include <cstdint>

constexpr int Sc = 2048, Dc = 64;
constexpr int BM = 128, BN = 64, NT = 256;
constexpr int STR = 72;  // halves per smem row (144B: +16B skew -> conflict-free ldmatrix)

// smem layout (half offsets): Q hi + double-buffered [Khi|Vhi] tiles
constexpr int QHI = 0;
constexpr int BUFH = 9216;            // halves per buffer: K 64*72 + V 64*72
constexpr int BUF0 = 9216;            // buffer b at BUF0 + b*BUFH; V at +4608 within
constexpr int SMEM_BYTES = (BUF0 + 2 * BUFH) * 2;  // 55296

#define DI __device__ __forceinline__

DI uint32_t h2u(__half2 h) { return *reinterpret_cast<uint32_t*>(&h); }

DI void mma16816(float* c, const uint32_t* a, const uint32_t* b) {
    asm volatile(
        "mma.sync.aligned.m16n8k16.row.col.f32.f16.f16.f32 "
        "{%0,%1,%2,%3}, {%4,%5,%6,%7}, {%8,%9}, {%0,%1,%2,%3};"
        : "+f"(c[0]), "+f"(c[1]), "+f"(c[2]), "+f"(c[3])
        : "r"(a[0]), "r"(a[1]), "r"(a[2]), "r"(a[3]), "r"(b[0]), "r"(b[1]));
}
DI void ldsm4(uint32_t* r, uint32_t a) {
    asm volatile("ldmatrix.sync.aligned.m8n8.x4.shared.b16 {%0,%1,%2,%3}, [%4];"
                 : "=r"(r[0]), "=r"(r[1]), "=r"(r[2]), "=r"(r[3]) : "r"(a));
}
DI void ldsm4t(uint32_t* r, uint32_t a) {
    asm volatile("ldmatrix.sync.aligned.m8n8.x4.trans.shared.b16 {%0,%1,%2,%3}, [%4];"
                 : "=r"(r[0]), "=r"(r[1]), "=r"(r[2]), "=r"(r[3]) : "r"(a));
}
DI float ex2(float x) { float y; asm("ex2.approx.ftz.f32 %0, %1;" : "=f"(y) : "f"(x)); return y; }

__global__ __launch_bounds__(NT, 2)
void fa_mma_kernel(const float* __restrict__ Q, const float* __restrict__ K,
                   const float* __restrict__ V, float* __restrict__ O) {
    extern __shared__ __half sm[];
    const int tid = threadIdx.x;
    const int lane = tid & 31, w = tid >> 5;
    const int r8 = lane & 7, g = lane >> 3;          // ldmatrix lane decomposition
    const int q4 = lane & 3, rr = lane >> 2;         // mma C-fragment decomposition
    const int head = blockIdx.y;
    const int m0 = (int)(gridDim.x - 1 - blockIdx.x) * BM;  // heavy tiles first
    const size_t hoff = (size_t)head * Sc * Dc;

    const uint32_t sb = (uint32_t)__cvta_generic_to_shared(sm);
    const uint32_t aq = sb + (uint32_t)(QHI + (16 * w + r8 + (g & 1) * 8) * STR + (g >> 1) * 8) * 2;
    // lane offsets relative to a buffer base (bytes)
    const uint32_t kb_rel = (uint32_t)((r8 + ((g >> 1) & 1) * 8) * STR + (g & 1) * 8) * 2;
    const uint32_t vb_rel = (uint32_t)(4608 + (r8 + (g & 1) * 8) * STR + (g >> 1) * 8) * 2;

    // ---- Q: load, scale, convert to fp16 in smem (once) ----
    constexpr float SC = 0.125f * 1.4426950408889634f;  // 1/sqrt(64) * log2(e)
#pragma unroll
    for (int i = 0; i < 8; ++i) {
        int idx = tid + NT * i;                 // 0..2047
        int row = idx >> 4, dg = idx & 15;      // d = 4*dg
        float4 t = reinterpret_cast<const float4*>(Q + hoff + (size_t)(m0 + row) * Dc)[dg];
        __half2* ph = reinterpret_cast<__half2*>(sm + QHI + row * STR + 4 * dg);
        ph[0] = __floats2half2_rn(t.x * SC, t.y * SC);
        ph[1] = __floats2half2_rn(t.z * SC, t.w * SC);
    }

    float oc[8][4];
#pragma unroll
    for (int j = 0; j < 8; ++j)
#pragma unroll
        for (int c = 0; c < 4; ++c) oc[j][c] = 0.0f;
    float mr0 = -1e30f, mr1 = -1e30f;
    float lr0 = 0.0f, lr1 = 0.0f;   // thread-local quad-partials; reduced once in epilogue

    const int row0 = m0 + 16 * w + rr, row1 = row0 + 8;
    const int ntiles = m0 / BN + 2;

    // per-thread convert targets (same for every tile; buffer base varies)
    const int cv_key = tid >> 4, cv_dg = tid & 15;   // thread -> (key base, dim group)

    // ---- prologue: convert tile 0 into buffer 0 ----
#pragma unroll
    for (int i = 0; i < 4; ++i) {
        int key = cv_key + i * 16;
        float4 t = reinterpret_cast<const float4*>(K + hoff + (size_t)key * Dc)[cv_dg];
        float4 u = reinterpret_cast<const float4*>(V + hoff + (size_t)key * Dc)[cv_dg];
        __half2* ph = reinterpret_cast<__half2*>(sm + BUF0 + key * STR + 4 * cv_dg);
        ph[0] = __floats2half2_rn(t.x, t.y);
        ph[1] = __floats2half2_rn(t.z, t.w);
        __half2* qh = reinterpret_cast<__half2*>(sm + BUF0 + 4608 + key * STR + 4 * cv_dg);
        qh[0] = __floats2half2_rn(u.x, u.y);
        qh[1] = __floats2half2_rn(u.z, u.w);
    }
    __syncthreads();

    for (int jt = 0; jt < ntiles; ++jt) {
        const int j0 = jt * BN;
        const uint32_t bufb = sb + (uint32_t)(BUF0 + (jt & 1) * BUFH) * 2;
        const uint32_t kbase = bufb + kb_rel;
        const uint32_t vbase = bufb + vb_rel;

        // ---- S = Qhi * Khi ----
        float sc[8][4];
#pragma unroll
        for (int j = 0; j < 8; ++j)
#pragma unroll
            for (int c = 0; c < 4; ++c) sc[j][c] = 0.0f;

#pragma unroll
        for (int t = 0; t < 4; ++t) {
            uint32_t ah[4];
            ldsm4(ah, aq + t * 32);
#pragma unroll
            for (int u = 0; u < 4; ++u) {
                uint32_t bh[4];
                ldsm4(bh, kbase + u * 2304 + t * 32);   // NON-trans: B[k][n] packed in k
                mma16816(sc[2 * u],     ah, bh);
                mma16816(sc[2 * u + 1], ah, bh + 2);
            }
        }

        // ---- convert tile jt+1 into the other buffer (overlaps softmax/PV below) ----
        if (jt + 1 < ntiles) {
            const int nbase = j0 + BN;
            __half* dst = sm + BUF0 + ((jt + 1) & 1) * BUFH;
#pragma unroll
            for (int i = 0; i < 4; ++i) {
                int key = cv_key + i * 16;
                float4 t = reinterpret_cast<const float4*>(K + hoff + (size_t)(nbase + key) * Dc)[cv_dg];
                float4 u = reinterpret_cast<const float4*>(V + hoff + (size_t)(nbase + key) * Dc)[cv_dg];
                __half2* ph = reinterpret_cast<__half2*>(dst + key * STR + 4 * cv_dg);
                ph[0] = __floats2half2_rn(t.x, t.y);
                ph[1] = __floats2half2_rn(t.z, t.w);
                __half2* qh = reinterpret_cast<__half2*>(dst + 4608 + key * STR + 4 * cv_dg);
                qh[0] = __floats2half2_rn(u.x, u.y);
                qh[1] = __floats2half2_rn(u.z, u.w);
            }
        }

        // ---- mask (diagonal tiles) + row max + quad max-reduce + rescale ----
        if (j0 + BN - 1 > m0) {
            const int col0 = j0 + 2 * q4;
#pragma unroll
            for (int j = 0; j < 8; ++j) {
                int c0 = col0 + 8 * j;
                sc[j][0] = (c0     <= row0) ? sc[j][0] : -1e30f;
                sc[j][1] = (c0 + 1 <= row0) ? sc[j][1] : -1e30f;
                sc[j][2] = (c0     <= row1) ? sc[j][2] : -1e30f;
                sc[j][3] = (c0 + 1 <= row1) ? sc[j][3] : -1e30f;
            }
        }
        float mx0 = -1e30f, mx1 = -1e30f;
#pragma unroll
        for (int j = 0; j < 8; ++j) {
            mx0 = fmaxf(mx0, fmaxf(sc[j][0], sc[j][1]));
            mx1 = fmaxf(mx1, fmaxf(sc[j][2], sc[j][3]));
        }
        mx0 = fmaxf(mx0, __shfl_xor_sync(0xffffffffu, mx0, 1));
        mx0 = fmaxf(mx0, __shfl_xor_sync(0xffffffffu, mx0, 2));
        mx1 = fmaxf(mx1, __shfl_xor_sync(0xffffffffu, mx1, 1));
        mx1 = fmaxf(mx1, __shfl_xor_sync(0xffffffffu, mx1, 2));
        const float mn0 = fmaxf(mr0, mx0), mn1 = fmaxf(mr1, mx1);
        const float al0 = ex2(mr0 - mn0), al1 = ex2(mr1 - mn1);
        mr0 = mn0; mr1 = mn1;

#pragma unroll
        for (int j = 0; j < 8; ++j) {
            oc[j][0] *= al0; oc[j][1] *= al0;
            oc[j][2] *= al1; oc[j][3] *= al1;
        }
        float s0 = 0.0f, s1 = 0.0f;

        // ---- fused softmax + PV per 16-key chunk: ex2 -> pack -> mma ----
#pragma unroll
        for (int t = 0; t < 4; ++t) {
            float p00 = ex2(sc[2 * t][0]     - mn0), p01 = ex2(sc[2 * t][1]     - mn0);
            float p02 = ex2(sc[2 * t][2]     - mn1), p03 = ex2(sc[2 * t][3]     - mn1);
            float p10 = ex2(sc[2 * t + 1][0] - mn0), p11 = ex2(sc[2 * t + 1][1] - mn0);
            float p12 = ex2(sc[2 * t + 1][2] - mn1), p13 = ex2(sc[2 * t + 1][3] - mn1);
            s0 += p00 + p01 + p10 + p11;
            s1 += p02 + p03 + p12 + p13;

            uint32_t ph[4];
            ph[0] = h2u(__floats2half2_rn(p00, p01));
            ph[1] = h2u(__floats2half2_rn(p02, p03));
            ph[2] = h2u(__floats2half2_rn(p10, p11));
            ph[3] = h2u(__floats2half2_rn(p12, p13));
#pragma unroll
            for (int j = 0; j < 8; j += 2) {
                uint32_t vh[4];
                ldsm4t(vh, vbase + t * 2304 + j * 16);  // trans: V rows (=k) -> B[k][n] packed in k
                mma16816(oc[j],     ph, vh);
                mma16816(oc[j + 1], ph, vh + 2);
            }
        }

        // thread-local l update (alpha is quad-uniform; reduce once at the end)
        lr0 = lr0 * al0 + s0;
        lr1 = lr1 * al1 + s1;

        __syncthreads();   // single barrier: publishes buf[(jt+1)&1], ends reads of buf[jt&1]
    }

    // ---- epilogue: quad-lane l reduction, normalize, store ----
    lr0 += __shfl_xor_sync(0xffffffffu, lr0, 1);
    lr0 += __shfl_xor_sync(0xffffffffu, lr0, 2);
    lr1 += __shfl_xor_sync(0xffffffffu, lr1, 1);
    lr1 += __shfl_xor_sync(0xffffffffu, lr1, 2);
    const float i0 = 1.0f / lr0, i1 = 1.0f / lr1;
#pragma unroll
    for (int j = 0; j < 8; ++j) {
        int col = 8 * j + 2 * q4;
        reinterpret_cast<float2*>(O + hoff + (size_t)row0 * Dc + col)[0] =
            make_float2(oc[j][0] * i0, oc[j][1] * i0);
        reinterpret_cast<float2*>(O + hoff + (size_t)row1 * Dc + col)[0] =
            make_float2(oc[j][2] * i1, oc[j][3] * i1);
    }
}

extern "C" void kernel_launch(void* const* d_in, const int* in_sizes, int n_in,
                              void* d_out, int out_size) {
    const float* q = (const float*)d_in[0];
    const float* k = (const float*)d_in[1];
    const float* v = (const float*)d_in[2];
    float* o = (float*)d_out;

    cudaFuncSetAttribute(fa_mma_kernel, cudaFuncAttributeMaxDynamicSharedMemorySize, SMEM_BYTES);
    dim3 grid(Sc / BM, 2 * 12);
    fa_mma_kernel<<<grid, NT, SMEM_BYTES>>>(q, k, v, o);
}